// round 6
// baseline (speedup 1.0000x reference)
#include <cuda_runtime.h>
#include <cuda_fp16.h>
#include <math.h>

// Problem constants
#define BZ 32
#define TT 256
#define HH 1024
#define C4 4096
#define NB 128            // step blocks
#define BROW 1032         // staged B row stride in halves (2064 B)
#define BMATB 66048       // bytes per staged 32x1024 fp16 matrix
#define PART_F (24 * 16 * 33)                 // partial floats (24 jobs x 16 rows x 33)
#define SMEM_STEP (2 * BMATB + PART_F * 4)    // 182784 B
#define SMEM_X0 66048

// ---------------------------------------------------------------------------
// Device scratch (static; no allocations)
// ---------------------------------------------------------------------------
__device__ __half g_Wt[2][C4][2048];          // transposed weights, fp16
__device__ uint4  g_WsA0[NB * 2 * 64 * 32];   // L0 step frags (W_hh0, K=1024)
__device__ uint4  g_WsA1[NB * 2 * 128 * 32];  // L1 step frags (K=2048)
__device__ uint4  g_Wx0[256 * 64 * 32];       // x0-gemm frags (W_ih0)
__device__ __half g_x[TT * BZ][1024];         // x re-laid [t*32+b][e]
__device__ __half g_hf[2][2][BZ][HH];         // [parity][layer][b][j]
__device__ float  g_h[2][HH][BZ];             // [L][j][b] (coalesced pointwise)
__device__ float  g_c[2][HH][BZ];
__device__ float  g_X0[(size_t)TT * C4 * BZ]; // x@W_ih0 + b0, [t][col][b]

// ---------------------------------------------------------------------------
// Helpers
// ---------------------------------------------------------------------------
__device__ __forceinline__ unsigned ldu(const __half* p) {
    return *reinterpret_cast<const unsigned*>(p);
}
__device__ __forceinline__ void mma16816(float d[4], const unsigned* a,
                                         unsigned b0, unsigned b1) {
    asm volatile(
        "mma.sync.aligned.m16n8k16.row.col.f32.f16.f16.f32 "
        "{%0,%1,%2,%3}, {%4,%5,%6,%7}, {%8,%9}, {%0,%1,%2,%3};\n"
        : "+f"(d[0]), "+f"(d[1]), "+f"(d[2]), "+f"(d[3])
        : "r"(a[0]), "r"(a[1]), "r"(a[2]), "r"(a[3]), "r"(b0), "r"(b1));
}
__device__ __forceinline__ void ldm4(unsigned r[4], unsigned addr) {
    asm volatile("ldmatrix.sync.aligned.m8n8.x4.shared.b16 {%0,%1,%2,%3}, [%4];"
                 : "=r"(r[0]), "=r"(r[1]), "=r"(r[2]), "=r"(r[3]) : "r"(addr));
}
__device__ __forceinline__ float sigf(float x) { return 1.f / (1.f + __expf(-x)); }
__device__ __forceinline__ float tanhfast(float x) {
    float e2 = __expf(-2.f * fabsf(x));
    return copysignf((1.f - e2) / (1.f + e2), x);
}

// ---------------------------------------------------------------------------
// Prep kernels
// ---------------------------------------------------------------------------
__global__ void prep_weights(const float* __restrict__ W_ih0,
                             const float* __restrict__ W_hh0,
                             const float* __restrict__ W_ih1,
                             const float* __restrict__ W_hh1)
{
    __shared__ float tile[32][33];
    int k0 = blockIdx.x * 32;
    int c0 = blockIdx.y * 32;
    int L  = blockIdx.z;
    int tx = threadIdx.x, ty = threadIdx.y;
#pragma unroll
    for (int i = 0; i < 4; i++) {
        int k = k0 + ty + i * 8;
        const float* S; int kr;
        if (L == 0) { if (k < HH) { S = W_hh0; kr = k; } else { S = W_ih0; kr = k - HH; } }
        else        { if (k < HH) { S = W_ih1; kr = k; } else { S = W_hh1; kr = k - HH; } }
        tile[ty + i * 8][tx] = S[(size_t)kr * C4 + c0 + tx];
    }
    __syncthreads();
#pragma unroll
    for (int i = 0; i < 4; i++) {
        int c = c0 + ty + i * 8;
        g_Wt[L][c][k0 + tx] = __float2half(tile[tx][ty + i * 8]);
    }
}

// Fragment packs. m-tile row mapping for step kernels: rows 0-7 -> gate (mt*2),
// rows 8-15 -> gate (mt*2+1), unit = blk*8 + r.
__global__ void swz_A0()
{
    const int idx = blockIdx.x * blockDim.x + threadIdx.x;   // 524288
    const int lane = idx & 31;
    const int ch   = (idx >> 5) & 63;
    const int mt   = (idx >> 11) & 1;
    const int blk  = idx >> 12;
    const int r  = lane >> 2;
    const int ka = (lane & 3) * 2;
    const int col0 = (mt * 2) * HH + blk * 8 + r;
    const int col1 = (mt * 2 + 1) * HH + blk * 8 + r;
    const int k0 = ch * 16 + ka;
    uint4 f;
    f.x = ldu(&g_Wt[0][col0][k0]);
    f.y = ldu(&g_Wt[0][col1][k0]);
    f.z = ldu(&g_Wt[0][col0][k0 + 8]);
    f.w = ldu(&g_Wt[0][col1][k0 + 8]);
    g_WsA0[idx] = f;
}

__global__ void swz_A1()
{
    const int idx = blockIdx.x * blockDim.x + threadIdx.x;   // 1048576
    const int lane = idx & 31;
    const int ch   = (idx >> 5) & 127;
    const int mt   = (idx >> 12) & 1;
    const int blk  = idx >> 13;
    const int r  = lane >> 2;
    const int ka = (lane & 3) * 2;
    const int col0 = (mt * 2) * HH + blk * 8 + r;
    const int col1 = (mt * 2 + 1) * HH + blk * 8 + r;
    const int k0 = ch * 16 + ka;
    uint4 f;
    f.x = ldu(&g_Wt[1][col0][k0]);
    f.y = ldu(&g_Wt[1][col1][k0]);
    f.z = ldu(&g_Wt[1][col0][k0 + 8]);
    f.w = ldu(&g_Wt[1][col1][k0 + 8]);
    g_WsA1[idx] = f;
}

// x0 frags keep the old sequential-cols mapping: col0 = mt*16 + r.
__global__ void swz_X0()
{
    const int idx = blockIdx.x * blockDim.x + threadIdx.x;   // 524288
    const int lane = idx & 31;
    const int ch   = (idx >> 5) & 63;
    const int mt   = idx >> 11;          // 0..255
    const int r  = lane >> 2;
    const int ka = (lane & 3) * 2;
    const int col0 = mt * 16 + r;
    const int col1 = col0 + 8;
    const int k0 = 1024 + ch * 16 + ka;
    uint4 f;
    f.x = ldu(&g_Wt[0][col0][k0]);
    f.y = ldu(&g_Wt[0][col1][k0]);
    f.z = ldu(&g_Wt[0][col0][k0 + 8]);
    f.w = ldu(&g_Wt[0][col1][k0 + 8]);
    g_Wx0[idx] = f;
}

__global__ void prep_x(const float* __restrict__ x)
{
    const int N = BZ * TT * 1024;
    for (int idx = blockIdx.x * blockDim.x + threadIdx.x; idx < N;
         idx += gridDim.x * blockDim.x) {
        int e  = idx & 1023;
        int bt = idx >> 10;
        int t  = bt & (TT - 1);
        int b  = bt >> 8;
        g_x[t * BZ + b][e] = __float2half(x[idx]);
    }
}

__global__ void zero_states()
{
    int idx = blockIdx.x * blockDim.x + threadIdx.x;
    const int nhf = 2 * 2 * BZ * HH;
    if (idx < nhf) (&g_hf[0][0][0][0])[idx] = __float2half(0.f);
    const int nf = 2 * HH * BZ;
    if (idx < nf) {
        (&g_h[0][0][0])[idx] = 0.f;
        (&g_c[0][0][0])[idx] = 0.f;
    }
}

__global__ void copy_mask(const float* __restrict__ m, float* __restrict__ dst)
{
    int i = blockIdx.x * blockDim.x + threadIdx.x;
    if (i < BZ * TT) dst[i] = m[i];
}

// ---------------------------------------------------------------------------
// X0 precompute: X0[t][col][b] = sum_e x[t,b,e]*W_ih0[e,col] + b0[col]
// ---------------------------------------------------------------------------
__global__ void __launch_bounds__(256) x0_gemm(const float* __restrict__ b0)
{
    extern __shared__ __align__(16) unsigned char sm[];
    const unsigned smbase = (unsigned)__cvta_generic_to_shared(sm);
    const int gX  = blockIdx.x;
    const int ty  = blockIdx.y;
    const int tid = threadIdx.x, lane = tid & 31, warp = tid >> 5;
    const int w = warp & 3, nh = warp >> 2;
    const int mt = w * 64 + gX;

    const uint4* __restrict__ A = g_Wx0 + (size_t)mt * 64 * 32 + lane;

    const int ltile = lane >> 3, lrow = lane & 7;
    const int nbb = (ltile >> 1) * 8 + lrow;
    const int kb  = (ltile & 1) * 8;
    const unsigned ldmb = smbase + (((nh * 16 + nbb) * BROW + kb) << 1);

    const int colr = mt * 16 + (lane >> 2);
    const float bia0 = b0[colr];
    const float bia8 = b0[colr + 8];

    for (int tt = 0; tt < 8; tt++) {
        const int t = ty * 8 + tt;
#pragma unroll
        for (int q = 0; q < 16; q++) {
            int idx = tid + q * 256;
            int row = idx >> 7, kc = idx & 127;
            const __half* src = &g_x[t * BZ + row][kc * 8];
            unsigned dst = smbase + row * 2064 + kc * 16;
            asm volatile("cp.async.cg.shared.global [%0], [%1], 16;\n"
                         :: "r"(dst), "l"(src));
        }
        asm volatile("cp.async.commit_group;\ncp.async.wait_group 0;\n");
        __syncthreads();

        float acc0[4] = {0, 0, 0, 0}, acc1[4] = {0, 0, 0, 0};
        uint4 Ac[4], An[4];
#pragma unroll
        for (int cc = 0; cc < 4; cc++) Ac[cc] = A[cc * 32];
        for (int ct = 0; ct < 16; ct++) {
            if (ct < 15) {
#pragma unroll
                for (int cc = 0; cc < 4; cc++) An[cc] = A[((ct + 1) * 4 + cc) * 32];
            }
#pragma unroll
            for (int cc = 0; cc < 4; cc++) {
                const int c = ct * 4 + cc;
                unsigned bb[4];
                ldm4(bb, ldmb + c * 32);
                const unsigned* ap = reinterpret_cast<const unsigned*>(&Ac[cc]);
                mma16816(acc0, ap, bb[0], bb[1]);
                mma16816(acc1, ap, bb[2], bb[3]);
            }
#pragma unroll
            for (int cc = 0; cc < 4; cc++) Ac[cc] = An[cc];
        }
        __syncthreads();

        const size_t base = (size_t)t * C4 * BZ;
        const int bc0 = nh * 16 + (lane & 3) * 2;
        g_X0[base + (size_t)colr * 32 + bc0]           = acc0[0] + bia0;
        g_X0[base + (size_t)colr * 32 + bc0 + 1]       = acc0[1] + bia0;
        g_X0[base + (size_t)(colr + 8) * 32 + bc0]     = acc0[2] + bia8;
        g_X0[base + (size_t)(colr + 8) * 32 + bc0 + 1] = acc0[3] + bia8;
        const int bc1 = bc0 + 8;
        g_X0[base + (size_t)colr * 32 + bc1]           = acc1[0] + bia0;
        g_X0[base + (size_t)colr * 32 + bc1 + 1]       = acc1[1] + bia0;
        g_X0[base + (size_t)(colr + 8) * 32 + bc1]     = acc1[2] + bia8;
        g_X0[base + (size_t)(colr + 8) * 32 + bc1 + 1] = acc1[3] + bia8;
    }
}

// ---------------------------------------------------------------------------
// One timestep. 128 blocks x 256 threads, perfectly balanced:
// block owns 8 L0 units (32 cols, K=1024) + 8 L1 units (32 cols, K=2048).
// Work = 24 jobs of (m16-tile x 16 k-chunks); warp w runs jobs
// {w (L1 mt0), 8+w (L1 mt1), 16+w (L0)}. Partials in dedicated SMEM, then
// fused pointwise update for both layers.
// ---------------------------------------------------------------------------
__global__ void __launch_bounds__(256) lstm_step(
    int t,
    const float* __restrict__ mask,
    const float* __restrict__ bias1,
    float* __restrict__ out)
{
    extern __shared__ __align__(16) unsigned char sm[];
    const unsigned smbase = (unsigned)__cvta_generic_to_shared(sm);
    float* part = reinterpret_cast<float*>(sm + 2 * BMATB);

    const int blk  = blockIdx.x;
    const int tid  = threadIdx.x;
    const int lane = tid & 31;
    const int w    = tid >> 5;
    const int p    = t & 1;

    // ---- stage h0, h1 (32 x 1024 fp16 each) ----
    const __half* __restrict__ h0 = &g_hf[p][0][0][0];
    const __half* __restrict__ h1 = &g_hf[p][1][0][0];
#pragma unroll
    for (int q = 0; q < 32; q++) {
        int idx = tid + q * 256;
        int mat = idx >> 12;
        int row = (idx >> 7) & 31, kc = idx & 127;
        const __half* src = (mat ? h1 : h0) + row * HH + kc * 8;
        unsigned dst = smbase + mat * BMATB + row * 2064 + kc * 16;
        asm volatile("cp.async.cg.shared.global [%0], [%1], 16;\n"
                     :: "r"(dst), "l"(src));
    }
    asm volatile("cp.async.commit_group;\ncp.async.wait_group 0;\n");
    __syncthreads();

    // ldmatrix lane geometry
    const int ltile = lane >> 3, lrow = lane & 7;
    const int nbb = (ltile >> 1) * 8 + lrow;
    const int kb  = (ltile & 1) * 8;

    // ---- 3 jobs for this warp ----
#pragma unroll
    for (int jj = 0; jj < 3; jj++) {
        int jobid, mat, kbase;
        const uint4* Aj;
        if (jj < 2) {                       // L1, m-tile jj, k-octant w
            jobid = jj * 8 + w;
            mat   = (w >= 4);
            kbase = (w & 3) * 256;
            Aj = g_WsA1 + ((size_t)(blk * 2 + jj) * 128 + w * 16) * 32 + lane;
        } else {                            // L0, m-tile (w>>2), k-quarter (w&3)
            jobid = 16 + w;
            mat   = 0;
            kbase = (w & 3) * 256;
            Aj = g_WsA0 + ((size_t)(blk * 2 + (w >> 2)) * 64 + (w & 3) * 16) * 32 + lane;
        }
        const unsigned mb = smbase + (mat ? BMATB : 0);
        const unsigned ldmb0 = mb + ((unsigned)((nbb) * BROW + kbase + kb) << 1);
        const unsigned ldmb1 = mb + ((unsigned)((16 + nbb) * BROW + kbase + kb) << 1);

        float acc[4][4];
#pragma unroll
        for (int j = 0; j < 4; j++)
#pragma unroll
            for (int q = 0; q < 4; q++) acc[j][q] = 0.f;

        uint4 Ac[4], An[4];
#pragma unroll
        for (int cc = 0; cc < 4; cc++) Ac[cc] = Aj[cc * 32];
#pragma unroll
        for (int ct = 0; ct < 4; ct++) {
            if (ct < 3) {
#pragma unroll
                for (int cc = 0; cc < 4; cc++) An[cc] = Aj[((ct + 1) * 4 + cc) * 32];
            }
#pragma unroll
            for (int cc = 0; cc < 4; cc++) {
                const int c = ct * 4 + cc;
                unsigned b01[4], b23[4];
                ldm4(b01, ldmb0 + c * 32);
                ldm4(b23, ldmb1 + c * 32);
                const unsigned* ap = reinterpret_cast<const unsigned*>(&Ac[cc]);
                mma16816(acc[0], ap, b01[0], b01[1]);
                mma16816(acc[1], ap, b01[2], b01[3]);
                mma16816(acc[2], ap, b23[0], b23[1]);
                mma16816(acc[3], ap, b23[2], b23[3]);
            }
#pragma unroll
            for (int cc = 0; cc < 4; cc++) Ac[cc] = An[cc];
        }

        // write partial [jobid][16][33]
        const int r  = lane >> 2;
        const int q2 = (lane & 3) * 2;
        float* pp = part + jobid * (16 * 33);
#pragma unroll
        for (int jn = 0; jn < 4; jn++) {
            const int n = jn * 8 + q2;
            pp[r * 33 + n]           = acc[jn][0];
            pp[r * 33 + n + 1]       = acc[jn][1];
            pp[(r + 8) * 33 + n]     = acc[jn][2];
            pp[(r + 8) * 33 + n + 1] = acc[jn][3];
        }
    }
    __syncthreads();

    // ---- fused pointwise: thread -> (unit u, batch b) for BOTH layers ----
    const int b = tid & 31;
    const int u = (tid >> 5) & 7;
    const int j = blk * 8 + u;
    const float m = mask[b * TT + t];

    // Layer 0: 4 k-partials per gate + X0
    {
        float gate[4];
#pragma unroll
        for (int q = 0; q < 4; q++) {
            const int row = (q & 1) * 8 + u;
            const float* pb = part + (16 + (q >> 1) * 4) * (16 * 33) + row * 33 + b;
            float v = pb[0] + pb[16 * 33] + pb[2 * 16 * 33] + pb[3 * 16 * 33];
            v += g_X0[(size_t)t * C4 * BZ + (size_t)(q * HH + j) * 32 + b];
            gate[q] = v;
        }
        const float cp = g_c[0][j][b];
        const float hp = g_h[0][j][b];
        float cn = sigf(gate[0]) * cp + sigf(gate[1]) * tanhfast(gate[3]);
        cn = cn * m + cp * (1.f - m);
        float hn = sigf(gate[2]) * tanhfast(cn);
        hn = hn * m + hp * (1.f - m);
        g_c[0][j][b] = cn;
        g_h[0][j][b] = hn;
        g_hf[p ^ 1][0][b][j] = __float2half(hn);
    }
    // Layer 1: 8 k-partials per gate + bias1
    {
        float gate[4];
#pragma unroll
        for (int q = 0; q < 4; q++) {
            const int row = (q & 1) * 8 + u;
            const float* pb = part + ((q >> 1) * 8) * (16 * 33) + row * 33 + b;
            float v = 0.f;
#pragma unroll
            for (int o = 0; o < 8; o++) v += pb[o * (16 * 33)];
            gate[q] = v + bias1[q * HH + j];
        }
        const float cp = g_c[1][j][b];
        const float hp = g_h[1][j][b];
        float cn = sigf(gate[0]) * cp + sigf(gate[1]) * tanhfast(gate[3]);
        cn = cn * m + cp * (1.f - m);
        float hn = sigf(gate[2]) * tanhfast(cn);
        hn = hn * m + hp * (1.f - m);
        g_c[1][j][b] = cn;
        g_h[1][j][b] = hn;
        g_hf[p ^ 1][1][b][j] = __float2half(hn);
        out[((size_t)b * TT + t) * HH + j] = hn;
    }
}

// ---------------------------------------------------------------------------
extern "C" void kernel_launch(void* const* d_in, const int* in_sizes, int n_in,
                              void* d_out, int out_size)
{
    const float* x     = (const float*)d_in[0];
    const float* mask  = (const float*)d_in[1];
    const float* W_ih0 = (const float*)d_in[2];
    const float* W_hh0 = (const float*)d_in[3];
    const float* bs0   = (const float*)d_in[4];
    const float* W_ih1 = (const float*)d_in[5];
    const float* W_hh1 = (const float*)d_in[6];
    const float* bs1   = (const float*)d_in[7];
    float* out = (float*)d_out;

    static bool attr_done = false;
    if (!attr_done) {
        cudaFuncSetAttribute(x0_gemm, cudaFuncAttributeMaxDynamicSharedMemorySize, SMEM_X0);
        cudaFuncSetAttribute(lstm_step, cudaFuncAttributeMaxDynamicSharedMemorySize, SMEM_STEP);
        attr_done = true;
    }

    prep_weights<<<dim3(2048 / 32, C4 / 32, 2), dim3(32, 8)>>>(W_ih0, W_hh0, W_ih1, W_hh1);
    swz_A0<<<524288 / 256, 256>>>();
    swz_A1<<<1048576 / 256, 256>>>();
    swz_X0<<<524288 / 256, 256>>>();
    prep_x<<<1024, 256>>>(x);
    zero_states<<<512, 256>>>();
    x0_gemm<<<dim3(64, 32), 256, SMEM_X0>>>(bs0);

    for (int t = 0; t < TT; t++) {
        lstm_step<<<NB, 256, SMEM_STEP>>>(t, mask, bs1, out);
    }

    if (out_size >= BZ * TT * HH + BZ * TT) {
        copy_mask<<<(BZ * TT + 255) / 256, 256>>>(mask, out + (size_t)BZ * TT * HH);
    }
}

// round 7
// speedup vs baseline: 1.3114x; 1.3114x over previous
#include <cuda_runtime.h>
#include <cuda_fp16.h>
#include <math.h>

// Problem constants
#define BZ 32
#define TT 256
#define EE 1024
#define HH 1024
#define KK 2048
#define C4 4096
#define NMT 256           // m-tiles (16 cols) per layer
#define NCHUNK 128        // k-chunks of 16
#define BROW 1032         // staged B row stride in halves (2064 B)
#define BMATB 66048       // bytes per staged 32x1024 fp16 matrix

// ---------------------------------------------------------------------------
// Device scratch (static; no allocations)
// ---------------------------------------------------------------------------
__device__ __half g_Wt[2][C4][KK];              // transposed weights, fp16
__device__ uint4  g_Wsw[2 * NMT * NCHUNK * 32]; // mma A fragments
__device__ __half g_x[TT * BZ][EE];             // x re-laid [t*32+b][e]
__device__ __half g_hf[2][2][BZ][HH];           // [parity][layer][b][j]
__device__ float  g_h[2][BZ][HH];
__device__ float  g_c[2][BZ][HH];
__device__ float  g_X0[(size_t)TT * C4 * BZ];   // x@W_ih0 + b0, [t][col][b]

// ---------------------------------------------------------------------------
// Helpers
// ---------------------------------------------------------------------------
__device__ __forceinline__ unsigned ldu(const __half* p) {
    return *reinterpret_cast<const unsigned*>(p);
}
__device__ __forceinline__ void mma16816(float d[4], const unsigned* a,
                                         unsigned b0, unsigned b1) {
    asm volatile(
        "mma.sync.aligned.m16n8k16.row.col.f32.f16.f16.f32 "
        "{%0,%1,%2,%3}, {%4,%5,%6,%7}, {%8,%9}, {%0,%1,%2,%3};\n"
        : "+f"(d[0]), "+f"(d[1]), "+f"(d[2]), "+f"(d[3])
        : "r"(a[0]), "r"(a[1]), "r"(a[2]), "r"(a[3]), "r"(b0), "r"(b1));
}
__device__ __forceinline__ void ldm4(unsigned r[4], unsigned addr) {
    asm volatile("ldmatrix.sync.aligned.m8n8.x4.shared.b16 {%0,%1,%2,%3}, [%4];"
                 : "=r"(r[0]), "=r"(r[1]), "=r"(r[2]), "=r"(r[3]) : "r"(addr));
}
__device__ __forceinline__ float sigf(float x) { return 1.f / (1.f + __expf(-x)); }
__device__ __forceinline__ float tanhfast(float x) {
    float e2 = __expf(-2.f * fabsf(x));
    return copysignf((1.f - e2) / (1.f + e2), x);
}

// ---------------------------------------------------------------------------
// Prep kernels
// ---------------------------------------------------------------------------
__global__ void prep_weights(const float* __restrict__ W_ih0,
                             const float* __restrict__ W_hh0,
                             const float* __restrict__ W_ih1,
                             const float* __restrict__ W_hh1)
{
    __shared__ float tile[32][33];
    int k0 = blockIdx.x * 32;
    int c0 = blockIdx.y * 32;
    int L  = blockIdx.z;
    int tx = threadIdx.x, ty = threadIdx.y;
#pragma unroll
    for (int i = 0; i < 4; i++) {
        int k = k0 + ty + i * 8;
        const float* S; int kr;
        if (L == 0) { if (k < HH) { S = W_hh0; kr = k; } else { S = W_ih0; kr = k - HH; } }
        else        { if (k < HH) { S = W_ih1; kr = k; } else { S = W_hh1; kr = k - HH; } }
        tile[ty + i * 8][tx] = S[(size_t)kr * C4 + c0 + tx];
    }
    __syncthreads();
#pragma unroll
    for (int i = 0; i < 4; i++) {
        int c = c0 + ty + i * 8;
        g_Wt[L][c][k0 + tx] = __float2half(tile[tx][ty + i * 8]);
    }
}

__global__ void swizzle_weights()
{
    const int idx  = blockIdx.x * blockDim.x + threadIdx.x;
    const int lane = idx & 31;
    const int c    = (idx >> 5)  & (NCHUNK - 1);
    const int mt   = (idx >> 12) & (NMT - 1);
    const int L    = (idx >> 20) & 1;
    const int r  = lane >> 2;
    const int ka = (lane & 3) * 2;
    const int col0 = mt * 16 + r;
    const int col1 = col0 + 8;
    const int k0 = c * 16 + ka;
    uint4 f;
    f.x = ldu(&g_Wt[L][col0][k0]);
    f.y = ldu(&g_Wt[L][col1][k0]);
    f.z = ldu(&g_Wt[L][col0][k0 + 8]);
    f.w = ldu(&g_Wt[L][col1][k0 + 8]);
    g_Wsw[idx] = f;
}

__global__ void prep_x(const float* __restrict__ x)
{
    const int N = BZ * TT * EE;
    for (int idx = blockIdx.x * blockDim.x + threadIdx.x; idx < N;
         idx += gridDim.x * blockDim.x) {
        int e  = idx & (EE - 1);
        int bt = idx >> 10;
        int t  = bt & (TT - 1);
        int b  = bt >> 8;
        g_x[t * BZ + b][e] = __float2half(x[idx]);
    }
}

__global__ void zero_states()
{
    int idx = blockIdx.x * blockDim.x + threadIdx.x;
    const int nhf = 2 * 2 * BZ * HH;
    if (idx < nhf) (&g_hf[0][0][0][0])[idx] = __float2half(0.f);
    const int nf = 2 * BZ * HH;
    if (idx < nf) {
        (&g_h[0][0][0])[idx] = 0.f;
        (&g_c[0][0][0])[idx] = 0.f;
    }
}

__global__ void copy_mask(const float* __restrict__ m, float* __restrict__ dst)
{
    int i = blockIdx.x * blockDim.x + threadIdx.x;
    if (i < BZ * TT) dst[i] = m[i];
}

// ---------------------------------------------------------------------------
// X0 precompute: X0[t][col][b] = sum_e x[t,b,e]*W_ih0[e,col] + b0[col]
// ---------------------------------------------------------------------------
__global__ void __launch_bounds__(256) x0_gemm(const float* __restrict__ b0)
{
    extern __shared__ __align__(16) unsigned char sm[];
    const unsigned smbase = (unsigned)__cvta_generic_to_shared(sm);
    const int gX  = blockIdx.x;
    const int ty  = blockIdx.y;
    const int tid = threadIdx.x, lane = tid & 31, warp = tid >> 5;
    const int w = warp & 3, nh = warp >> 2;
    const int mt = w * 64 + gX;

    const uint4* __restrict__ A = g_Wsw + ((size_t)mt * NCHUNK + 64) * 32 + lane;

    const int ltile = lane >> 3, lrow = lane & 7;
    const int nbb = (ltile >> 1) * 8 + lrow;
    const int kb  = (ltile & 1) * 8;
    const unsigned ldmb = smbase + (((nh * 16 + nbb) * BROW + kb) << 1);

    const int colr = mt * 16 + (lane >> 2);
    const float bia0 = b0[colr];
    const float bia8 = b0[colr + 8];

    for (int tt = 0; tt < 8; tt++) {
        const int t = ty * 8 + tt;
#pragma unroll
        for (int q = 0; q < 16; q++) {
            int idx = tid + q * 256;
            int row = idx >> 7, kc = idx & 127;
            const __half* src = &g_x[t * BZ + row][kc * 8];
            unsigned dst = smbase + row * 2064 + kc * 16;
            asm volatile("cp.async.ca.shared.global [%0], [%1], 16;\n"
                         :: "r"(dst), "l"(src));
        }
        asm volatile("cp.async.commit_group;\ncp.async.wait_group 0;\n");
        __syncthreads();

        float acc0[4] = {0, 0, 0, 0}, acc1[4] = {0, 0, 0, 0};
        uint4 Ac[4], An[4];
#pragma unroll
        for (int cc = 0; cc < 4; cc++) Ac[cc] = A[cc * 32];
        for (int ct = 0; ct < 16; ct++) {
            if (ct < 15) {
#pragma unroll
                for (int cc = 0; cc < 4; cc++) An[cc] = A[((ct + 1) * 4 + cc) * 32];
            }
#pragma unroll
            for (int cc = 0; cc < 4; cc++) {
                const int c = ct * 4 + cc;
                unsigned bb[4];
                ldm4(bb, ldmb + c * 32);
                const unsigned* ap = reinterpret_cast<const unsigned*>(&Ac[cc]);
                mma16816(acc0, ap, bb[0], bb[1]);
                mma16816(acc1, ap, bb[2], bb[3]);
            }
#pragma unroll
            for (int cc = 0; cc < 4; cc++) Ac[cc] = An[cc];
        }
        __syncthreads();

        const size_t base = (size_t)t * C4 * BZ;
        const int bc0 = nh * 16 + (lane & 3) * 2;
        g_X0[base + (size_t)colr * 32 + bc0]           = acc0[0] + bia0;
        g_X0[base + (size_t)colr * 32 + bc0 + 1]       = acc0[1] + bia0;
        g_X0[base + (size_t)(colr + 8) * 32 + bc0]     = acc0[2] + bia8;
        g_X0[base + (size_t)(colr + 8) * 32 + bc0 + 1] = acc0[3] + bia8;
        const int bc1 = bc0 + 8;
        g_X0[base + (size_t)colr * 32 + bc1]           = acc1[0] + bia0;
        g_X0[base + (size_t)colr * 32 + bc1 + 1]       = acc1[1] + bia0;
        g_X0[base + (size_t)(colr + 8) * 32 + bc1]     = acc1[2] + bia8;
        g_X0[base + (size_t)(colr + 8) * 32 + bc1 + 1] = acc1[3] + bia8;
    }
}

// ---------------------------------------------------------------------------
// One timestep (R4 structure + latency hiding). 128 blocks x 256 threads.
//   bx <  64: layer0, 64 cols, K=1024 (x-part precomputed into g_X0)
//   bx >= 64: layer1, 64 cols, K=2048
// L1 staging is split: warp-group hf stages & consumes matrix hf, synced by
// its own named barrier -> mma starts after 64 KB lands, not 132 KB.
// A fragments + all pointwise operands prefetched before the staging wait.
// ---------------------------------------------------------------------------
__global__ void __launch_bounds__(256) lstm_step(
    int t,
    const float* __restrict__ mask,
    const float* __restrict__ bias1,
    float* __restrict__ out)
{
    extern __shared__ __align__(16) unsigned char sm[];
    const unsigned smbase = (unsigned)__cvta_generic_to_shared(sm);
    float* preS = reinterpret_cast<float*>(sm);    // aliased after mma: [2][64][33]

    const int bx   = blockIdx.x;
    const int L    = bx >> 6;
    const int g    = bx & 63;
    const int tid  = threadIdx.x;
    const int lane = tid & 31;
    const int warp = tid >> 5;
    const int w    = warp & 3;
    const int hf   = warp >> 2;
    const int p    = t & 1;

    // ---- issue B staging (no wait yet) ----
    const __half* __restrict__ h0 = &g_hf[p][0][0][0];
    const __half* __restrict__ h1 = &g_hf[p][1][0][0];
    if (L == 0) {
        // all 256 threads stage h0
#pragma unroll
        for (int q = 0; q < 16; q++) {
            int idx = tid + q * 256;
            int row = idx >> 7, kc = idx & 127;
            const __half* src = h0 + row * HH + kc * 8;
            unsigned dst = smbase + row * 2064 + kc * 16;
            asm volatile("cp.async.ca.shared.global [%0], [%1], 16;\n"
                         :: "r"(dst), "l"(src));
        }
    } else {
        // warp-group hf stages matrix hf (h0 or h1) with 128 threads
        const __half* __restrict__ srcm = hf ? h1 : h0;
        const int tg = tid & 127;
#pragma unroll
        for (int q = 0; q < 32; q++) {
            int idx = tg + q * 128;
            int row = idx >> 7, kc = idx & 127;
            const __half* src = srcm + row * HH + kc * 8;
            unsigned dst = smbase + hf * BMATB + row * 2064 + kc * 16;
            asm volatile("cp.async.ca.shared.global [%0], [%1], 16;\n"
                         :: "r"(dst), "l"(src));
        }
    }
    asm volatile("cp.async.commit_group;\n");

    // ---- A pointers + preload first chunks BEFORE the staging wait ----
    const int mt      = w * 64 + g;
    const int cbase   = L ? hf * 64 : hf * 32;
    const int niter   = L ? 16 : 8;
    const uint4* __restrict__ A =
        g_Wsw + (((size_t)L * NMT + mt) * NCHUNK + cbase) * 32 + lane;

    uint4 Ac[4], An[4];
#pragma unroll
    for (int cc = 0; cc < 4; cc++) Ac[cc] = A[cc * 32];

    // ---- pointwise operand prefetch (independent of staging) ----
    float mpre[2], cpre[2], hpre[2], addp[2][4];
#pragma unroll
    for (int it = 0; it < 2; it++) {
        const int e  = tid + it * 256;
        const int b  = e >> 4;
        const int ul = e & 15;
        const int j  = g * 16 + ul;
        mpre[it] = mask[b * TT + t];
        cpre[it] = g_c[L][b][j];
        hpre[it] = g_h[L][b][j];
        if (L == 0) {
            const size_t xb = (size_t)t * C4 * BZ + b;
#pragma unroll
            for (int q = 0; q < 4; q++)
                addp[it][q] = g_X0[xb + (size_t)(q * HH + j) * 32];
        } else {
#pragma unroll
            for (int q = 0; q < 4; q++)
                addp[it][q] = bias1[q * HH + j];
        }
    }

    // ldmatrix lane geometry
    const int ltile = lane >> 3, lrow = lane & 7;
    const int nbb = (ltile >> 1) * 8 + lrow;
    const int kb  = (ltile & 1) * 8;
    const unsigned matoff = L ? hf * BMATB : hf * 1024;
    unsigned ldmb[2];
#pragma unroll
    for (int ng = 0; ng < 2; ng++)
        ldmb[ng] = smbase + matoff + (((ng * 16 + nbb) * BROW + kb) << 1);

    // ---- wait for my staged half ----
    asm volatile("cp.async.wait_group 0;\n");
    if (L == 0) {
        __syncthreads();
    } else {
        if (hf == 0) asm volatile("bar.sync 1, 128;\n" ::: "memory");
        else         asm volatile("bar.sync 2, 128;\n" ::: "memory");
    }

    // ---- mma ----
    float acc[4][4];
#pragma unroll
    for (int j = 0; j < 4; j++)
#pragma unroll
        for (int q = 0; q < 4; q++) acc[j][q] = 0.f;

    for (int ct = 0; ct < niter; ct++) {
        if (ct + 1 < niter) {
#pragma unroll
            for (int cc = 0; cc < 4; cc++) An[cc] = A[((ct + 1) * 4 + cc) * 32];
        }
#pragma unroll
        for (int cc = 0; cc < 4; cc++) {
            const int c = ct * 4 + cc;
            unsigned b01[4], b23[4];
            ldm4(b01, ldmb[0] + c * 32);
            ldm4(b23, ldmb[1] + c * 32);
            const unsigned* ap = reinterpret_cast<const unsigned*>(&Ac[cc]);
            mma16816(acc[0], ap, b01[0], b01[1]);
            mma16816(acc[1], ap, b01[2], b01[3]);
            mma16816(acc[2], ap, b23[0], b23[1]);
            mma16816(acc[3], ap, b23[2], b23[3]);
        }
#pragma unroll
        for (int cc = 0; cc < 4; cc++) Ac[cc] = An[cc];
    }
    __syncthreads();   // all B reads done before preS aliases over the buffers

    // ---- reduce partials via SMEM ----
    {
        const int r = lane >> 2;
        const int q = (lane & 3) * 2;
        float* pS = preS + hf * (64 * 33);
#pragma unroll
        for (int j = 0; j < 4; j++) {
            const int n = j * 8 + q;
            pS[(w * 16 + r) * 33 + n]         = acc[j][0];
            pS[(w * 16 + r) * 33 + n + 1]     = acc[j][1];
            pS[(w * 16 + r + 8) * 33 + n]     = acc[j][2];
            pS[(w * 16 + r + 8) * 33 + n + 1] = acc[j][3];
        }
    }
    __syncthreads();

    // ---- fused pointwise LSTM update (operands prefetched) ----
#pragma unroll
    for (int it = 0; it < 2; it++) {
        const int e  = tid + it * 256;
        const int b  = e >> 4;
        const int ul = e & 15;
        const int j  = g * 16 + ul;
        float f  = preS[ul * 33 + b]        + preS[64 * 33 + ul * 33 + b]        + addp[it][0];
        float i  = preS[(16 + ul) * 33 + b] + preS[64 * 33 + (16 + ul) * 33 + b] + addp[it][1];
        float o  = preS[(32 + ul) * 33 + b] + preS[64 * 33 + (32 + ul) * 33 + b] + addp[it][2];
        float gg = preS[(48 + ul) * 33 + b] + preS[64 * 33 + (48 + ul) * 33 + b] + addp[it][3];
        const float m  = mpre[it];
        const float cp = cpre[it];
        const float hp = hpre[it];

        float cn = sigf(f) * cp + sigf(i) * tanhfast(gg);
        cn = cn * m + cp * (1.f - m);
        float hn = sigf(o) * tanhfast(cn);
        hn = hn * m + hp * (1.f - m);

        g_c[L][b][j] = cn;
        g_h[L][b][j] = hn;
        g_hf[p ^ 1][L][b][j] = __float2half(hn);
        if (L) out[((size_t)b * TT + t) * HH + j] = hn;
    }
}

// ---------------------------------------------------------------------------
extern "C" void kernel_launch(void* const* d_in, const int* in_sizes, int n_in,
                              void* d_out, int out_size)
{
    const float* x     = (const float*)d_in[0];
    const float* mask  = (const float*)d_in[1];
    const float* W_ih0 = (const float*)d_in[2];
    const float* W_hh0 = (const float*)d_in[3];
    const float* bs0   = (const float*)d_in[4];
    const float* W_ih1 = (const float*)d_in[5];
    const float* W_hh1 = (const float*)d_in[6];
    const float* bs1   = (const float*)d_in[7];
    float* out = (float*)d_out;

    static bool attr_done = false;
    if (!attr_done) {
        cudaFuncSetAttribute(x0_gemm, cudaFuncAttributeMaxDynamicSharedMemorySize, BMATB);
        cudaFuncSetAttribute(lstm_step, cudaFuncAttributeMaxDynamicSharedMemorySize, 2 * BMATB);
        attr_done = true;
    }

    prep_weights<<<dim3(KK / 32, C4 / 32, 2), dim3(32, 8)>>>(W_ih0, W_hh0, W_ih1, W_hh1);
    swizzle_weights<<<(2 * NMT * NCHUNK * 32) / 256, 256>>>();
    prep_x<<<1024, 256>>>(x);
    zero_states<<<512, 256>>>();
    x0_gemm<<<dim3(64, 32), 256, BMATB>>>(bs0);

    for (int t = 0; t < TT; t++) {
        lstm_step<<<128, 256, 2 * BMATB>>>(t, mask, bs1, out);
    }

    if (out_size >= BZ * TT * HH + BZ * TT) {
        copy_mask<<<(BZ * TT + 255) / 256, 256>>>(mask, out + (size_t)BZ * TT * HH);
    }
}